// round 7
// baseline (speedup 1.0000x reference)
#include <cuda_runtime.h>
#include <cuda_fp16.h>
#include <cstdint>

// DeformableFusionAcrossFocus via mma.sync fp16 (HMMA), R6: 8-site CTA, 2 CTAs/SM,
// packed B (2x LDS.128/chunk), unroll-2 chunk loop.
// B=2, C=64, N=16, H=W=96, K=3. CTA = 8 w-sites, 8 warps, warp = 1 site (16 M rows).
// GEMM: D[m=n', col] = sum_c X[c,n'] * W[col,c]
//   cols 0..191  : Z_k[o]  (k=col>>6, o=col&63), W = w_def[o][c][k]
//   cols 192..209: Zoff    (kk=(col-192)/6, j=(col-192)%6), W = w_off[j][c][kk]
//   cols 210..215: zero pad         (27 chunks of 8 cols)
// 2-pass fp16 A-split: (Ah + Al) * B, fp32 accumulate.

#define HW 9216

// ---- smem byte layout ----
#define SM_BFA  0                    // [chunk27][lane32] uint4 (ks0,ks1) = 13824
#define SM_BFB  13824                // [chunk27][lane32] uint4 (ks2,ks3) = 13824
#define SM_SCR  27648                // X staging 64*140 floats = 35840; reused Zw / STG2
#define SM_BD   63488                // 64 floats
#define SM_BO   63744                // 6 floats (+pad)
#define SMEM_TOTAL 63776

__device__ __forceinline__ void mma16816(float& d0, float& d1, float& d2, float& d3,
                                         uint4 a, uint2 b) {
    asm volatile(
        "mma.sync.aligned.m16n8k16.row.col.f32.f16.f16.f32 "
        "{%0,%1,%2,%3}, {%4,%5,%6,%7}, {%8,%9}, {%0,%1,%2,%3};"
        : "+f"(d0), "+f"(d1), "+f"(d2), "+f"(d3)
        : "r"(a.x), "r"(a.y), "r"(a.z), "r"(a.w), "r"(b.x), "r"(b.y));
}

__device__ __forceinline__ uint32_t pkh(__half h0, __half h1) {
    return (uint32_t)__half_as_ushort(h0) | ((uint32_t)__half_as_ushort(h1) << 16);
}
__device__ __forceinline__ uint32_t pkhs(float v0, float v1, uint32_t& lo) {
    __half h0 = __float2half_rn(v0), h1 = __float2half_rn(v1);
    float r0 = v0 - __half2float(h0);
    float r1 = v1 - __half2float(h1);
    lo = pkh(__float2half_rn(r0), __float2half_rn(r1));
    return pkh(h0, h1);
}

__global__ void __launch_bounds__(256, 2)
deform_hmma4_kernel(const float* __restrict__ x,
                    const float* __restrict__ w_off,
                    const float* __restrict__ b_off,
                    const float* __restrict__ w_def,
                    const float* __restrict__ b_def,
                    float* __restrict__ out)
{
    extern __shared__ char smem[];
    uint4* BFA = (uint4*)(smem + SM_BFA);
    uint4* BFB = (uint4*)(smem + SM_BFB);
    float* SCR = (float*)(smem + SM_SCR);
    float* BD  = (float*)(smem + SM_BD);
    float* BO  = (float*)(smem + SM_BO);

    const int tid  = threadIdx.x;
    const int wid  = tid >> 5;        // warp = local site (0..7)
    const int lane = tid & 31;
    const int g    = lane >> 2;       // fragment row group
    const int q    = lane & 3;        // fragment col group

    const int bid = blockIdx.x;       // 0..2303
    const int b   = bid / 1152;
    const int h   = (bid / 12) % 96;
    const int w0  = (bid % 12) * 8;
    const long xbase = (long)b * (64 * 16 * HW) + (long)h * 96 + w0;

    if (tid < 64) BD[tid] = b_def[tid];
    if (tid < 6)  BO[tid] = b_off[tid];

    // ---------------- stage X[c][s][n] -> SCR[c*140 + s*17 + n] ----------------
    {
        const float* xb = x + xbase;
        #pragma unroll 8
        for (int i = tid; i < 8192; i += 256) {
            int s = i & 7, n = (i >> 3) & 15, c = i >> 7;
            SCR[c * 140 + s * 17 + n] = xb[(long)(c * 16 + n) * HW + s];
        }
    }

    // ---------------- B fragments (fp16) from gmem, packed per-lane ----------------
    for (int idx = tid; idx < 27 * 4 * 32; idx += 256) {
        int l = idx & 31, rem = idx >> 5;
        int ks = rem & 3, chunk = rem >> 2;
        int ncol = chunk * 8 + (l >> 2);
        int c0 = ks * 16 + (l & 3) * 2;
        float v[4];
        #pragma unroll
        for (int i = 0; i < 4; i++) {
            int c = c0 + (i >> 1) * 8 + (i & 1);
            float w = 0.f;
            if (ncol < 192) {
                int kk = ncol >> 6, o = ncol & 63;
                w = __ldg(w_def + o * 192 + c * 3 + kk);
            } else if (ncol < 210) {
                int t = ncol - 192, kk = t / 6, j = t - 6 * kk;
                w = __ldg(w_off + j * 192 + c * 3 + kk);
            }
            v[i] = w;
        }
        uint2 pk = make_uint2(pkh(__float2half_rn(v[0]), __float2half_rn(v[1])),
                              pkh(__float2half_rn(v[2]), __float2half_rn(v[3])));
        uint2* dst = (ks < 2) ? (uint2*)&BFA[chunk * 32 + l] : (uint2*)&BFB[chunk * 32 + l];
        dst[ks & 1] = pk;
    }
    __syncthreads();   // X staging + B fragments visible

    // ---------------- A fragments -> registers (warp's own site, fp16 hi/lo) ----------------
    uint4 ah[4], al[4];
    {
        const float* base = SCR + wid * 17;
        #pragma unroll
        for (int ks = 0; ks < 4; ks++) {
            int c0 = ks * 16 + q * 2;
            float v0 = base[(c0    ) * 140 + g    ];
            float v1 = base[(c0 + 1) * 140 + g    ];
            float v2 = base[(c0    ) * 140 + g + 8];
            float v3 = base[(c0 + 1) * 140 + g + 8];
            float v4 = base[(c0 + 8) * 140 + g    ];
            float v5 = base[(c0 + 9) * 140 + g    ];
            float v6 = base[(c0 + 8) * 140 + g + 8];
            float v7 = base[(c0 + 9) * 140 + g + 8];
            uint32_t la0, la1, la2, la3;
            uint32_t a0 = pkhs(v0, v1, la0);
            uint32_t a1 = pkhs(v2, v3, la1);
            uint32_t a2 = pkhs(v4, v5, la2);
            uint32_t a3 = pkhs(v6, v7, la3);
            ah[ks] = make_uint4(a0, a1, a2, a3);
            al[ks] = make_uint4(la0, la1, la2, la3);
        }
    }
    __syncthreads();   // X staging consumed; SCR reusable as Zw

    const uint4* BFAl = BFA + lane;
    const uint4* BFBl = BFB + lane;
    float* Zw = SCR + wid * 1088;      // 16 rows x 68 (Z) / 16 x 24 (offsets)
    const int n  = lane & 15;
    const int oh = lane >> 4;          // o half
    float* zlo = Zw + g * 68 + q * 2;  // hoisted store bases (Z layout)
    float* zhi = Zw + (g + 8) * 68 + q * 2;

    // ---------------- offsets (chunks 24..26) ----------------
    #pragma unroll
    for (int c3 = 0; c3 < 3; c3++) {
        const int chunk = 24 + c3;
        uint4 ba = BFAl[chunk * 32];
        uint4 bb = BFBl[chunk * 32];
        float p0 = 0.f, p1 = 0.f, p2 = 0.f, p3 = 0.f;
        float r0 = 0.f, r1 = 0.f, r2 = 0.f, r3 = 0.f;
        mma16816(p0, p1, p2, p3, ah[0], make_uint2(ba.x, ba.y));
        mma16816(r0, r1, r2, r3, ah[2], make_uint2(bb.x, bb.y));
        mma16816(p0, p1, p2, p3, al[0], make_uint2(ba.x, ba.y));
        mma16816(r0, r1, r2, r3, al[2], make_uint2(bb.x, bb.y));
        mma16816(p0, p1, p2, p3, ah[1], make_uint2(ba.z, ba.w));
        mma16816(r0, r1, r2, r3, ah[3], make_uint2(bb.z, bb.w));
        mma16816(p0, p1, p2, p3, al[1], make_uint2(ba.z, ba.w));
        mma16816(r0, r1, r2, r3, al[3], make_uint2(bb.z, bb.w));
        int cb = c3 * 8 + q * 2;
        *(float2*)(Zw + (g    ) * 24 + cb) = make_float2(p0 + r0, p1 + r1);
        *(float2*)(Zw + (g + 8) * 24 + cb) = make_float2(p2 + r2, p3 + r3);
    }
    __syncwarp();

    // ---------------- interpolation coefficients (lane owns row n) ----------------
    float W0c[3], W1c[3];
    int   s0c[3], s1c[3];
    {
        float offv[6];
        #pragma unroll
        for (int j = 0; j < 6; j++) {
            float v = BO[j];
            #pragma unroll
            for (int kk = 0; kk < 3; kk++) {
                int np = n - 1 + kk;
                if (np >= 0 && np < 16)
                    v += Zw[np * 24 + kk * 6 + j];
            }
            offv[j] = v;
        }
        #pragma unroll
        for (int k = 0; k < 3; k++) {
            float px  = (float)(n - 1 + k) + offv[2 * k + 1];
            float x0f = floorf(px);
            float fx  = px - x0f;
            int x0i = (int)x0f, x1i = x0i + 1;
            float wy = fmaxf(0.f, 1.f - fabsf(offv[2 * k]));
            W0c[k] = (x0i >= 0 && x0i < 16) ? (1.f - fx) * wy : 0.f;
            W1c[k] = (x1i >= 0 && x1i < 16) ? fx * wy : 0.f;
            s0c[k] = min(max(x0i, 0), 15);
            s1c[k] = min(max(x1i, 0), 15);
        }
    }
    __syncwarp();   // offsets consumed; Zw free for Z tiles

    // ---------------- output accumulators (o = oh*32 + i) ----------------
    float acco[32];
    #pragma unroll
    for (int j = 0; j < 8; j++) {
        float4 bd4 = ((const float4*)BD)[oh * 8 + j];
        acco[4 * j + 0] = bd4.x; acco[4 * j + 1] = bd4.y;
        acco[4 * j + 2] = bd4.z; acco[4 * j + 3] = bd4.w;
    }

    // ---------------- Z_k tiles + gather epilogue ----------------
    #pragma unroll 1
    for (int g3 = 0; g3 < 3; g3++) {
        #pragma unroll 2
        for (int cc = 0; cc < 8; cc++) {
            const int chunk = g3 * 8 + cc;
            uint4 ba = BFAl[chunk * 32];
            uint4 bb = BFBl[chunk * 32];
            float p0 = 0.f, p1 = 0.f, p2 = 0.f, p3 = 0.f;
            float r0 = 0.f, r1 = 0.f, r2 = 0.f, r3 = 0.f;
            mma16816(p0, p1, p2, p3, ah[0], make_uint2(ba.x, ba.y));
            mma16816(r0, r1, r2, r3, ah[2], make_uint2(bb.x, bb.y));
            mma16816(p0, p1, p2, p3, al[0], make_uint2(ba.x, ba.y));
            mma16816(r0, r1, r2, r3, al[2], make_uint2(bb.x, bb.y));
            mma16816(p0, p1, p2, p3, ah[1], make_uint2(ba.z, ba.w));
            mma16816(r0, r1, r2, r3, ah[3], make_uint2(bb.z, bb.w));
            mma16816(p0, p1, p2, p3, al[1], make_uint2(ba.z, ba.w));
            mma16816(r0, r1, r2, r3, al[3], make_uint2(bb.z, bb.w));
            *(float2*)(zlo + cc * 8) = make_float2(p0 + r0, p1 + r1);
            *(float2*)(zhi + cc * 8) = make_float2(p2 + r2, p3 + r3);
        }
        __syncwarp();

        {
            const float* t0 = Zw + s0c[g3] * 68 + oh * 32;
            const float* t1 = Zw + s1c[g3] * 68 + oh * 32;
            const float Wa = W0c[g3], Wb = W1c[g3];
            #pragma unroll
            for (int j = 0; j < 8; j++) {
                float4 g0 = ((const float4*)t0)[j];
                float4 g1 = ((const float4*)t1)[j];
                acco[4 * j + 0] += Wa * g0.x + Wb * g1.x;
                acco[4 * j + 1] += Wa * g0.y + Wb * g1.y;
                acco[4 * j + 2] += Wa * g0.z + Wb * g1.z;
                acco[4 * j + 3] += Wa * g0.w + Wb * g1.w;
            }
        }
        __syncwarp();
    }

    // ---------------- staged coalesced store ----------------
    // STG2[on*8 + f], f = wid ^ ((n>>2) | (oh<<2))  (injective per bank group)
    __syncthreads();   // all warps done with Zw
    {
        float* STG2 = SCR;
        const int f = wid ^ ((n >> 2) | (oh << 2));
        #pragma unroll
        for (int i = 0; i < 32; i++) {
            int on = (oh * 32 + i) * 16 + n;
            STG2[on * 8 + f] = acco[i];
        }
    }
    __syncthreads();
    {
        const float* STG2 = SCR;
        float* ob = out + xbase;
        #pragma unroll 8
        for (int idx = tid; idx < 8192; idx += 256) {
            int s = idx & 7, on = idx >> 3;
            int f = s ^ (((on >> 2) & 3) | ((on >> 9) << 2));
            ob[(long)on * HW + s] = STG2[on * 8 + f];
        }
    }
}

extern "C" void kernel_launch(void* const* d_in, const int* in_sizes, int n_in,
                              void* d_out, int out_size)
{
    const float* x     = (const float*)d_in[0];
    const float* w_off = (const float*)d_in[1];
    const float* b_off = (const float*)d_in[2];
    const float* w_def = (const float*)d_in[3];
    const float* b_def = (const float*)d_in[4];
    float* out = (float*)d_out;

    cudaFuncSetAttribute(deform_hmma4_kernel,
                         cudaFuncAttributeMaxDynamicSharedMemorySize, SMEM_TOTAL);

    // 2 (B) * 96 (H) * 12 (W/8) = 2304 CTAs, 256 threads, 2 CTAs/SM
    deform_hmma4_kernel<<<2304, 256, SMEM_TOTAL>>>(x, w_off, b_off, w_def, b_def, out);
}

// round 8
// speedup vs baseline: 1.0823x; 1.0823x over previous
#include <cuda_runtime.h>
#include <cuda_fp16.h>
#include <cstdint>

// DeformableFusionAcrossFocus via mma.sync fp16 (HMMA), R7:
// R5 shape (512 thr, 16 warps, 1 site/warp) + packed B LDS.128 + unroll-2 chunk loop
// + f32x2 packed gather epilogue.
// GEMM: D[m=n', col] = sum_c X[c,n'] * W[col,c]
//   cols 0..191  : Z_k[o]  (k=col>>6, o=col&63), W = w_def[o][c][k]
//   cols 192..209: Zoff    (kk=(col-192)/6, j=(col-192)%6), W = w_off[j][c][kk]
//   cols 210..215: zero pad         (27 chunks of 8 cols)
// 2-pass fp16 A-split: (Ah + Al) * B, fp32 accumulate.

#define HW 9216

// ---- smem byte layout ----
#define SM_BFA  0                    // [chunk27][lane32] uint4 (ks0,ks1) = 13824
#define SM_BFB  13824                // [chunk27][lane32] uint4 (ks2,ks3) = 13824
#define SM_SCR  27648                // X staging 64*276 floats = 70656; reused Zw / STG2
#define SM_BD   98304                // 64 floats
#define SM_BO   98560                // 6 floats (+pad)
#define SMEM_TOTAL 98592

typedef unsigned long long ull;

__device__ __forceinline__ void mma16816(float& d0, float& d1, float& d2, float& d3,
                                         uint4 a, uint2 b) {
    asm volatile(
        "mma.sync.aligned.m16n8k16.row.col.f32.f16.f16.f32 "
        "{%0,%1,%2,%3}, {%4,%5,%6,%7}, {%8,%9}, {%0,%1,%2,%3};"
        : "+f"(d0), "+f"(d1), "+f"(d2), "+f"(d3)
        : "r"(a.x), "r"(a.y), "r"(a.z), "r"(a.w), "r"(b.x), "r"(b.y));
}

__device__ __forceinline__ uint32_t pkh(__half h0, __half h1) {
    return (uint32_t)__half_as_ushort(h0) | ((uint32_t)__half_as_ushort(h1) << 16);
}
__device__ __forceinline__ uint32_t pkhs(float v0, float v1, uint32_t& lo) {
    __half h0 = __float2half_rn(v0), h1 = __float2half_rn(v1);
    float r0 = v0 - __half2float(h0);
    float r1 = v1 - __half2float(h1);
    lo = pkh(__float2half_rn(r0), __float2half_rn(r1));
    return pkh(h0, h1);
}

__device__ __forceinline__ ull pk2(float x, float y) {
    ull r; asm("mov.b64 %0, {%1, %2};" : "=l"(r) : "f"(x), "f"(y)); return r;
}
__device__ __forceinline__ void upk2(ull v, float& x, float& y) {
    asm("mov.b64 {%0, %1}, %2;" : "=f"(x), "=f"(y) : "l"(v));
}
__device__ __forceinline__ void fma2(ull& d, ull a, ull b) {
    asm("fma.rn.f32x2 %0, %1, %2, %0;" : "+l"(d) : "l"(a), "l"(b));
}

__global__ void __launch_bounds__(512, 1)
deform_hmma5_kernel(const float* __restrict__ x,
                    const float* __restrict__ w_off,
                    const float* __restrict__ b_off,
                    const float* __restrict__ w_def,
                    const float* __restrict__ b_def,
                    float* __restrict__ out)
{
    extern __shared__ char smem[];
    uint4* BFA = (uint4*)(smem + SM_BFA);
    uint4* BFB = (uint4*)(smem + SM_BFB);
    float* SCR = (float*)(smem + SM_SCR);
    float* BD  = (float*)(smem + SM_BD);
    float* BO  = (float*)(smem + SM_BO);

    const int tid  = threadIdx.x;
    const int wid  = tid >> 5;        // warp = local site (0..15)
    const int lane = tid & 31;
    const int g    = lane >> 2;       // fragment row group
    const int q    = lane & 3;        // fragment col group

    const int bid = blockIdx.x;       // 0..1151
    const int b   = bid / 576;
    const int h   = (bid / 6) % 96;
    const int w0  = (bid % 6) * 16;
    const long xbase = (long)b * (64 * 16 * HW) + (long)h * 96 + w0;

    if (tid < 64) BD[tid] = b_def[tid];
    if (tid < 6)  BO[tid] = b_off[tid];

    // ---------------- stage X[c][s][n] -> SCR[c*276 + s*17 + n] ----------------
    {
        const float* xb = x + xbase;
        #pragma unroll 8
        for (int i = tid; i < 16384; i += 512) {
            int s = i & 15, n = (i >> 4) & 15, c = i >> 8;
            SCR[c * 276 + s * 17 + n] = xb[(long)(c * 16 + n) * HW + s];
        }
    }

    // ---------------- B fragments (fp16) from gmem, packed per-lane ----------------
    for (int idx = tid; idx < 27 * 4 * 32; idx += 512) {
        int l = idx & 31, rem = idx >> 5;
        int ks = rem & 3, chunk = rem >> 2;
        int ncol = chunk * 8 + (l >> 2);
        int c0 = ks * 16 + (l & 3) * 2;
        float v[4];
        #pragma unroll
        for (int i = 0; i < 4; i++) {
            int c = c0 + (i >> 1) * 8 + (i & 1);
            float w = 0.f;
            if (ncol < 192) {
                int kk = ncol >> 6, o = ncol & 63;
                w = __ldg(w_def + o * 192 + c * 3 + kk);
            } else if (ncol < 210) {
                int t = ncol - 192, kk = t / 6, j = t - 6 * kk;
                w = __ldg(w_off + j * 192 + c * 3 + kk);
            }
            v[i] = w;
        }
        uint2 pk = make_uint2(pkh(__float2half_rn(v[0]), __float2half_rn(v[1])),
                              pkh(__float2half_rn(v[2]), __float2half_rn(v[3])));
        uint2* dst = (ks < 2) ? (uint2*)&BFA[chunk * 32 + l] : (uint2*)&BFB[chunk * 32 + l];
        dst[ks & 1] = pk;
    }
    __syncthreads();   // X staging + B fragments visible

    // ---------------- A fragments -> registers (warp's own site, fp16 hi/lo) ----------------
    uint4 ah[4], al[4];
    {
        const float* base = SCR + wid * 17;
        #pragma unroll
        for (int ks = 0; ks < 4; ks++) {
            int c0 = ks * 16 + q * 2;
            float v0 = base[(c0    ) * 276 + g    ];
            float v1 = base[(c0 + 1) * 276 + g    ];
            float v2 = base[(c0    ) * 276 + g + 8];
            float v3 = base[(c0 + 1) * 276 + g + 8];
            float v4 = base[(c0 + 8) * 276 + g    ];
            float v5 = base[(c0 + 9) * 276 + g    ];
            float v6 = base[(c0 + 8) * 276 + g + 8];
            float v7 = base[(c0 + 9) * 276 + g + 8];
            uint32_t la0, la1, la2, la3;
            uint32_t a0 = pkhs(v0, v1, la0);
            uint32_t a1 = pkhs(v2, v3, la1);
            uint32_t a2 = pkhs(v4, v5, la2);
            uint32_t a3 = pkhs(v6, v7, la3);
            ah[ks] = make_uint4(a0, a1, a2, a3);
            al[ks] = make_uint4(la0, la1, la2, la3);
        }
    }
    __syncthreads();   // X staging consumed; SCR reusable as Zw

    const uint4* BFAl = BFA + lane;
    const uint4* BFBl = BFB + lane;
    float* Zw = SCR + wid * 1088;      // 16 rows x 68 (Z) / 16 x 24 (offsets)
    const int n  = lane & 15;
    const int oh = lane >> 4;          // o half
    float* zlo = Zw + g * 68 + q * 2;  // hoisted Z store bases
    float* zhi = Zw + (g + 8) * 68 + q * 2;

    // ---------------- offsets (chunks 24..26) ----------------
    #pragma unroll
    for (int c3 = 0; c3 < 3; c3++) {
        const int chunk = 24 + c3;
        uint4 ba = BFAl[chunk * 32];
        uint4 bb = BFBl[chunk * 32];
        float p0 = 0.f, p1 = 0.f, p2 = 0.f, p3 = 0.f;
        float r0 = 0.f, r1 = 0.f, r2 = 0.f, r3 = 0.f;
        mma16816(p0, p1, p2, p3, ah[0], make_uint2(ba.x, ba.y));
        mma16816(r0, r1, r2, r3, ah[2], make_uint2(bb.x, bb.y));
        mma16816(p0, p1, p2, p3, al[0], make_uint2(ba.x, ba.y));
        mma16816(r0, r1, r2, r3, al[2], make_uint2(bb.x, bb.y));
        mma16816(p0, p1, p2, p3, ah[1], make_uint2(ba.z, ba.w));
        mma16816(r0, r1, r2, r3, ah[3], make_uint2(bb.z, bb.w));
        mma16816(p0, p1, p2, p3, al[1], make_uint2(ba.z, ba.w));
        mma16816(r0, r1, r2, r3, al[3], make_uint2(bb.z, bb.w));
        int cb = c3 * 8 + q * 2;
        *(float2*)(Zw + (g    ) * 24 + cb) = make_float2(p0 + r0, p1 + r1);
        *(float2*)(Zw + (g + 8) * 24 + cb) = make_float2(p2 + r2, p3 + r3);
    }
    __syncwarp();

    // ---------------- interpolation coefficients (lane owns row n) ----------------
    float W0c[3], W1c[3];
    int   s0c[3], s1c[3];
    {
        float offv[6];
        #pragma unroll
        for (int j = 0; j < 6; j++) {
            float v = BO[j];
            #pragma unroll
            for (int kk = 0; kk < 3; kk++) {
                int np = n - 1 + kk;
                if (np >= 0 && np < 16)
                    v += Zw[np * 24 + kk * 6 + j];
            }
            offv[j] = v;
        }
        #pragma unroll
        for (int k = 0; k < 3; k++) {
            float px  = (float)(n - 1 + k) + offv[2 * k + 1];
            float x0f = floorf(px);
            float fx  = px - x0f;
            int x0i = (int)x0f, x1i = x0i + 1;
            float wy = fmaxf(0.f, 1.f - fabsf(offv[2 * k]));
            W0c[k] = (x0i >= 0 && x0i < 16) ? (1.f - fx) * wy : 0.f;
            W1c[k] = (x1i >= 0 && x1i < 16) ? fx * wy : 0.f;
            s0c[k] = min(max(x0i, 0), 15);
            s1c[k] = min(max(x1i, 0), 15);
        }
    }
    __syncwarp();   // offsets consumed; Zw free for Z tiles

    // ---------------- packed output accumulators (o = oh*32 + 2j, 2j+1) ----------------
    ull acc2[16];
    #pragma unroll
    for (int j = 0; j < 16; j++) {
        float2 bd2 = ((const float2*)BD)[oh * 16 + j];
        acc2[j] = pk2(bd2.x, bd2.y);
    }

    // ---------------- Z_k tiles + packed gather epilogue ----------------
    #pragma unroll 1
    for (int g3 = 0; g3 < 3; g3++) {
        #pragma unroll 2
        for (int cc = 0; cc < 8; cc++) {
            const int chunk = g3 * 8 + cc;
            uint4 ba = BFAl[chunk * 32];
            uint4 bb = BFBl[chunk * 32];
            float p0 = 0.f, p1 = 0.f, p2 = 0.f, p3 = 0.f;
            float r0 = 0.f, r1 = 0.f, r2 = 0.f, r3 = 0.f;
            mma16816(p0, p1, p2, p3, ah[0], make_uint2(ba.x, ba.y));
            mma16816(r0, r1, r2, r3, ah[2], make_uint2(bb.x, bb.y));
            mma16816(p0, p1, p2, p3, al[0], make_uint2(ba.x, ba.y));
            mma16816(r0, r1, r2, r3, al[2], make_uint2(bb.x, bb.y));
            mma16816(p0, p1, p2, p3, ah[1], make_uint2(ba.z, ba.w));
            mma16816(r0, r1, r2, r3, ah[3], make_uint2(bb.z, bb.w));
            mma16816(p0, p1, p2, p3, al[1], make_uint2(ba.z, ba.w));
            mma16816(r0, r1, r2, r3, al[3], make_uint2(bb.z, bb.w));
            *(float2*)(zlo + cc * 8) = make_float2(p0 + r0, p1 + r1);
            *(float2*)(zhi + cc * 8) = make_float2(p2 + r2, p3 + r3);
        }
        __syncwarp();

        {
            const ulonglong2* t0 = (const ulonglong2*)(Zw + s0c[g3] * 68 + oh * 32);
            const ulonglong2* t1 = (const ulonglong2*)(Zw + s1c[g3] * 68 + oh * 32);
            const ull wa2 = pk2(W0c[g3], W0c[g3]);
            const ull wb2 = pk2(W1c[g3], W1c[g3]);
            #pragma unroll
            for (int j = 0; j < 8; j++) {
                ulonglong2 z0 = t0[j];
                ulonglong2 z1 = t1[j];
                fma2(acc2[2 * j    ], wa2, z0.x);
                fma2(acc2[2 * j + 1], wa2, z0.y);
                fma2(acc2[2 * j    ], wb2, z1.x);
                fma2(acc2[2 * j + 1], wb2, z1.y);
            }
        }
        __syncwarp();
    }

    // ---------------- staged coalesced store ----------------
    __syncthreads();   // all warps done with Zw
    {
        float* STG2 = SCR;
        const int f = wid ^ n;         // swizzle
        #pragma unroll
        for (int j = 0; j < 16; j++) {
            float va, vb;
            upk2(acc2[j], va, vb);
            int o = oh * 32 + 2 * j;
            STG2[(o * 16 + n) * 16 + f]       = va;
            STG2[((o + 1) * 16 + n) * 16 + f] = vb;
        }
    }
    __syncthreads();
    {
        const float* STG2 = SCR;
        float* ob = out + xbase;
        #pragma unroll 8
        for (int idx = tid; idx < 16384; idx += 512) {
            int s = idx & 15, on = idx >> 4;
            ob[(long)on * HW + s] = STG2[on * 16 + (s ^ (on & 15))];
        }
    }
}

extern "C" void kernel_launch(void* const* d_in, const int* in_sizes, int n_in,
                              void* d_out, int out_size)
{
    const float* x     = (const float*)d_in[0];
    const float* w_off = (const float*)d_in[1];
    const float* b_off = (const float*)d_in[2];
    const float* w_def = (const float*)d_in[3];
    const float* b_def = (const float*)d_in[4];
    float* out = (float*)d_out;

    cudaFuncSetAttribute(deform_hmma5_kernel,
                         cudaFuncAttributeMaxDynamicSharedMemorySize, SMEM_TOTAL);

    // 2 (B) * 96 (H) * 6 (W/16) = 1152 CTAs, 512 threads
    deform_hmma5_kernel<<<1152, 512, SMEM_TOTAL>>>(x, w_off, b_off, w_def, b_def, out);
}

// round 9
// speedup vs baseline: 1.2134x; 1.1211x over previous
#include <cuda_runtime.h>
#include <cuda_fp16.h>
#include <cstdint>

// DeformableFusionAcrossFocus R8: two-stage HMMA, gather-as-MMA.
// Stage 1 (per site-warp): Z^T[m=o-col, n'] = sum_c W[m,c] * X[c,n']   (A=weights, B=X)
//   m 0..191: Z_k (k=m>>6, o=m&63);  m 192..209: offset conv rows;  m 210..223: pad.
//   2-pass X split (Xh+Xl) fp16, W single fp16.
// Stage 2: out[o,n] += Z^T[o,s] * G[s,n],  G = interp matrix (2 nnz/col), fp16 Gh+Gl split.
//   Z^T D-frags convert directly to A-frags (same layout) — no smem round-trip.

#define HW 9216

// ---- smem byte layout ----
#define SM_WF    0        // weight A-frags [oc14][ks4][lane32] uint4 = 28672
#define SM_SCR   28672    // X staging 17664 floats = 70656B; reused as STG2 (16384 floats)
#define SM_ZOFF  99328    // per-warp offset buffer: 16 * 384 floats = 24576B
#define SM_BD    123904   // 64 floats
#define SM_BO    124160   // 6 floats (+pad)
#define SMEM_TOTAL 124192

__device__ __forceinline__ void mma16816(float& d0, float& d1, float& d2, float& d3,
                                         uint4 a, uint2 b) {
    asm volatile(
        "mma.sync.aligned.m16n8k16.row.col.f32.f16.f16.f32 "
        "{%0,%1,%2,%3}, {%4,%5,%6,%7}, {%8,%9}, {%0,%1,%2,%3};"
        : "+f"(d0), "+f"(d1), "+f"(d2), "+f"(d3)
        : "r"(a.x), "r"(a.y), "r"(a.z), "r"(a.w), "r"(b.x), "r"(b.y));
}

// pack two f32 -> f16x2 {lo=vlo, hi=vhi}
__device__ __forceinline__ uint32_t pk16(float vlo, float vhi) {
    uint32_t r;
    asm("cvt.rn.f16x2.f32 %0, %1, %2;" : "=r"(r) : "f"(vhi), "f"(vlo));
    return r;
}
__device__ __forceinline__ float2 h2f2(uint32_t h) {
    __half2 hh = *reinterpret_cast<__half2*>(&h);
    return __half22float2(hh);
}

__device__ __forceinline__ float wval(int m, int c,
                                      const float* __restrict__ w_def,
                                      const float* __restrict__ w_off) {
    if (m < 192) { int kk = m >> 6, o = m & 63; return __ldg(w_def + o * 192 + c * 3 + kk); }
    if (m < 210) { int t = m - 192; int kk = t / 6, j = t - 6 * kk;
                   return __ldg(w_off + j * 192 + c * 3 + kk); }
    return 0.f;
}

__global__ void __launch_bounds__(512, 1)
deform_hmma6_kernel(const float* __restrict__ x,
                    const float* __restrict__ w_off,
                    const float* __restrict__ b_off,
                    const float* __restrict__ w_def,
                    const float* __restrict__ b_def,
                    float* __restrict__ out)
{
    extern __shared__ char smem[];
    uint4*  WF  = (uint4*)(smem + SM_WF);
    float*  SCR = (float*)(smem + SM_SCR);
    float*  ZOF = (float*)(smem + SM_ZOFF);
    float*  BD  = (float*)(smem + SM_BD);
    float*  BO  = (float*)(smem + SM_BO);

    const int tid  = threadIdx.x;
    const int wid  = tid >> 5;        // warp = local site (0..15)
    const int lane = tid & 31;
    const int g    = lane >> 2;       // fragment row group
    const int q    = lane & 3;        // fragment col group

    const int bid = blockIdx.x;       // 0..1151
    const int b   = bid / 576;
    const int h   = (bid / 6) % 96;
    const int w0  = (bid % 6) * 16;
    const long xbase = (long)b * (64 * 16 * HW) + (long)h * 96 + w0;

    if (tid < 64) BD[tid] = b_def[tid];
    if (tid < 6)  BO[tid] = b_off[tid];

    // ---------------- stage X[c][s][n] -> SCR[c*276 + s*17 + n] ----------------
    {
        const float* xb = x + xbase;
        #pragma unroll 8
        for (int i = tid; i < 16384; i += 512) {
            int s = i & 15, n = (i >> 4) & 15, c = i >> 8;
            SCR[c * 276 + s * 17 + n] = xb[(long)(c * 16 + n) * HW + s];
        }
    }

    // ---------------- weight A-fragments (fp16 single) ----------------
    // A-frag m16k16: a0={w[g][2q,2q+1]}, a1={w[g+8][2q,2q+1]}, a2={w[g][2q+8,+9]}, a3={w[g+8][...]}
    for (int idx = tid; idx < 14 * 4 * 32; idx += 512) {
        int l = idx & 31, rem = idx >> 5;
        int ks = rem & 3, oc = rem >> 2;
        int qq = l & 3, gg = l >> 2;
        int c0 = ks * 16 + qq * 2;
        int m0 = oc * 16 + gg, m1 = m0 + 8;
        uint32_t a0 = pk16(wval(m0, c0,     w_def, w_off), wval(m0, c0 + 1, w_def, w_off));
        uint32_t a1 = pk16(wval(m1, c0,     w_def, w_off), wval(m1, c0 + 1, w_def, w_off));
        uint32_t a2 = pk16(wval(m0, c0 + 8, w_def, w_off), wval(m0, c0 + 9, w_def, w_off));
        uint32_t a3 = pk16(wval(m1, c0 + 8, w_def, w_off), wval(m1, c0 + 9, w_def, w_off));
        WF[(oc * 4 + ks) * 32 + l] = make_uint4(a0, a1, a2, a3);
    }
    __syncthreads();

    // ---------------- X B-fragments -> registers (hi/lo split) ----------------
    // B-frag k16n8 (tile t over n' = t*8+g): b0={X[2q][n'],X[2q+1][n']}, b1={X[2q+8][n'],X[2q+9][n']}
    uint2 bh[2][4], bl[2][4];
    {
        const float* base = SCR + wid * 17;
        #pragma unroll
        for (int t = 0; t < 2; t++) {
            const int nn = t * 8 + g;
            #pragma unroll
            for (int ks = 0; ks < 4; ks++) {
                int c0 = ks * 16 + q * 2;
                float v0 = base[(c0    ) * 276 + nn];
                float v1 = base[(c0 + 1) * 276 + nn];
                float v2 = base[(c0 + 8) * 276 + nn];
                float v3 = base[(c0 + 9) * 276 + nn];
                uint32_t h01 = pk16(v0, v1);
                uint32_t h23 = pk16(v2, v3);
                float2 f01 = h2f2(h01);
                float2 f23 = h2f2(h23);
                bh[t][ks] = make_uint2(h01, h23);
                bl[t][ks] = make_uint2(pk16(v0 - f01.x, v1 - f01.y),
                                       pk16(v2 - f23.x, v3 - f23.y));
            }
        }
    }

    // ---------------- offsets: stage-1 on oc 12,13, stash to ZOF ----------------
    float* zoff = ZOF + wid * 384;    // rows 0..17, stride 20
    #pragma unroll
    for (int oo = 0; oo < 2; oo++) {
        const int ocg = 12 + oo;
        uint4 au[4];
        #pragma unroll
        for (int ks = 0; ks < 4; ks++) au[ks] = WF[(ocg * 4 + ks) * 32 + lane];
        float d00 = 0.f, d01 = 0.f, d02 = 0.f, d03 = 0.f;
        float d10 = 0.f, d11 = 0.f, d12 = 0.f, d13 = 0.f;
        #pragma unroll
        for (int ks = 0; ks < 4; ks++) {
            mma16816(d00, d01, d02, d03, au[ks], bh[0][ks]);
            mma16816(d10, d11, d12, d13, au[ks], bh[1][ks]);
            mma16816(d00, d01, d02, d03, au[ks], bl[0][ks]);
            mma16816(d10, d11, d12, d13, au[ks], bl[1][ks]);
        }
        int r0 = oo * 16 + g;
        if (r0 < 18) {
            *(float2*)(zoff + r0 * 20 + q * 2)     = make_float2(d00, d01);
            *(float2*)(zoff + r0 * 20 + q * 2 + 8) = make_float2(d10, d11);
        }
        int r1 = r0 + 8;
        if (r1 < 18) {
            *(float2*)(zoff + r1 * 20 + q * 2)     = make_float2(d02, d03);
            *(float2*)(zoff + r1 * 20 + q * 2 + 8) = make_float2(d12, d13);
        }
    }
    __syncwarp();

    // ---------------- interpolation coefficients (lane owns n = lane&15) ----------------
    const int n = lane & 15;
    float W0c[3], W1c[3];
    int   s0c[3], s1c[3];
    {
        float offv[6];
        #pragma unroll
        for (int j = 0; j < 6; j++) {
            float v = BO[j];
            #pragma unroll
            for (int kk = 0; kk < 3; kk++) {
                int np = n - 1 + kk;
                if (np >= 0 && np < 16)
                    v += zoff[(kk * 6 + j) * 20 + np];
            }
            offv[j] = v;
        }
        #pragma unroll
        for (int k = 0; k < 3; k++) {
            float px  = (float)(n - 1 + k) + offv[2 * k + 1];
            float x0f = floorf(px);
            float fx  = px - x0f;
            int x0i = (int)x0f, x1i = x0i + 1;
            float wy = fmaxf(0.f, 1.f - fabsf(offv[2 * k]));
            W0c[k] = (x0i >= 0 && x0i < 16) ? (1.f - fx) * wy : 0.f;
            W1c[k] = (x1i >= 0 && x1i < 16) ? fx * wy : 0.f;
            s0c[k] = min(max(x0i, 0), 15);
            s1c[k] = min(max(x1i, 0), 15);
        }
    }

    // ---------------- output accumulators: out[o = oc*16+g(+8)][n = t*8+2q(+1)] ----------------
    float oa[4][2][4];
    #pragma unroll
    for (int oc = 0; oc < 4; oc++) {
        float bd0 = BD[oc * 16 + g];
        float bd1 = BD[oc * 16 + g + 8];
        #pragma unroll
        for (int t = 0; t < 2; t++) {
            oa[oc][t][0] = bd0; oa[oc][t][1] = bd0;
            oa[oc][t][2] = bd1; oa[oc][t][3] = bd1;
        }
    }

    // ---------------- main: per k, stage-1 GEMM + stage-2 gather-MMA ----------------
    #pragma unroll
    for (int k3 = 0; k3 < 3; k3++) {
        // build G B-frags: G[s][n] = W0(n)*(s==s0(n)) + W1(n)*(s==s1(n)), split hi/lo
        uint2 gh[2], gl[2];
        #pragma unroll
        for (int t = 0; t < 2; t++) {
            int nn = t * 8 + g;
            float w0v = __shfl_sync(0xffffffffu, W0c[k3], nn);
            float w1v = __shfl_sync(0xffffffffu, W1c[k3], nn);
            int   s0v = __shfl_sync(0xffffffffu, s0c[k3], nn);
            int   s1v = __shfl_sync(0xffffffffu, s1c[k3], nn);
            float gv[4];
            #pragma unroll
            for (int i = 0; i < 4; i++) {
                int s = q * 2 + (i & 1) + (i >> 1) * 8;
                gv[i] = ((s == s0v) ? w0v : 0.f) + ((s == s1v) ? w1v : 0.f);
            }
            uint32_t h01 = pk16(gv[0], gv[1]);
            uint32_t h23 = pk16(gv[2], gv[3]);
            float2 f01 = h2f2(h01);
            float2 f23 = h2f2(h23);
            gh[t] = make_uint2(h01, h23);
            gl[t] = make_uint2(pk16(gv[0] - f01.x, gv[1] - f01.y),
                               pk16(gv[2] - f23.x, gv[3] - f23.y));
        }

        #pragma unroll
        for (int oc = 0; oc < 4; oc++) {
            const int ocg = k3 * 4 + oc;
            uint4 au[4];
            #pragma unroll
            for (int ks = 0; ks < 4; ks++) au[ks] = WF[(ocg * 4 + ks) * 32 + lane];
            float d00 = 0.f, d01 = 0.f, d02 = 0.f, d03 = 0.f;
            float d10 = 0.f, d11 = 0.f, d12 = 0.f, d13 = 0.f;
            #pragma unroll
            for (int ks = 0; ks < 4; ks++) {
                mma16816(d00, d01, d02, d03, au[ks], bh[0][ks]);
                mma16816(d10, d11, d12, d13, au[ks], bh[1][ks]);
                mma16816(d00, d01, d02, d03, au[ks], bl[0][ks]);
                mma16816(d10, d11, d12, d13, au[ks], bl[1][ks]);
            }
            // Z^T D-frag -> stage-2 A-frag (fp16), layouts match directly
            uint4 za = make_uint4(pk16(d00, d01), pk16(d02, d03),
                                  pk16(d10, d11), pk16(d12, d13));
            mma16816(oa[oc][0][0], oa[oc][0][1], oa[oc][0][2], oa[oc][0][3], za, gh[0]);
            mma16816(oa[oc][0][0], oa[oc][0][1], oa[oc][0][2], oa[oc][0][3], za, gl[0]);
            mma16816(oa[oc][1][0], oa[oc][1][1], oa[oc][1][2], oa[oc][1][3], za, gh[1]);
            mma16816(oa[oc][1][0], oa[oc][1][1], oa[oc][1][2], oa[oc][1][3], za, gl[1]);
        }
    }

    // ---------------- staged coalesced store ----------------
    __syncthreads();   // everyone done with SCR (X staging) and ZOF
    {
        float* STG2 = SCR;
        #pragma unroll
        for (int oc = 0; oc < 4; oc++) {
            #pragma unroll
            for (int t = 0; t < 2; t++) {
                #pragma unroll
                for (int r = 0; r < 4; r++) {
                    int o  = oc * 16 + g + ((r >> 1) << 3);
                    int nn = t * 8 + 2 * q + (r & 1);
                    int ph = (o & 7) | (((nn >> 1) & 1) << 3);
                    STG2[(o * 16 + nn) * 16 + (wid ^ ph)] = oa[oc][t][r];
                }
            }
        }
    }
    __syncthreads();
    {
        const float* STG2 = SCR;
        float* ob = out + xbase;
        #pragma unroll 8
        for (int idx = tid; idx < 16384; idx += 512) {
            int s = idx & 15, on = idx >> 4;
            int o = on >> 4, nn = on & 15;
            int ph = (o & 7) | (((nn >> 1) & 1) << 3);
            ob[(long)on * HW + s] = STG2[on * 16 + (s ^ ph)];
        }
    }
}

extern "C" void kernel_launch(void* const* d_in, const int* in_sizes, int n_in,
                              void* d_out, int out_size)
{
    const float* x     = (const float*)d_in[0];
    const float* w_off = (const float*)d_in[1];
    const float* b_off = (const float*)d_in[2];
    const float* w_def = (const float*)d_in[3];
    const float* b_def = (const float*)d_in[4];
    float* out = (float*)d_out;

    cudaFuncSetAttribute(deform_hmma6_kernel,
                         cudaFuncAttributeMaxDynamicSharedMemorySize, SMEM_TOTAL);

    // 2 (B) * 96 (H) * 6 (W/16) = 1152 CTAs, 512 threads
    deform_hmma6_kernel<<<1152, 512, SMEM_TOTAL>>>(x, w_off, b_off, w_def, b_def, out);
}

// round 10
// speedup vs baseline: 1.3466x; 1.1098x over previous
#include <cuda_runtime.h>
#include <cuda_fp16.h>
#include <cstdint>

// DeformableFusionAcrossFocus R9: two-stage HMMA, gather-as-MMA, single-pass X.
// Stage 1 (per site-warp): Z^T[m=o-col, n'] = sum_c W[m,c] * X[c,n']   (A=weights fp16, B=X fp16)
//   m 0..191: Z_k (k=m>>6, o=m&63);  m 192..209: offset conv rows;  m 210..223: pad.
// Stage 2: out[o,n] += Z^T[o,s] * G[s,n],  G = interp matrix (2 nnz/col), fp16 Gh+Gl split.
//   Z^T D-frags convert directly to stage-2 A-frags (same layout) — no smem round-trip.
// Error budget: W-quant ~4e-4 + X-quant ~4e-4 (quadrature) ≈ 6e-4 < 1e-3.

#define HW 9216

// ---- smem byte layout ----
#define SM_WF    0        // weight A-frags [oc14][ks4][lane32] uint4 = 28672
#define SM_SCR   28672    // X staging 17664 floats = 70656B; reused as STG2 (16384 floats)
#define SM_ZOFF  99328    // per-warp offset buffer: 16 * 384 floats = 24576B
#define SM_BD    123904   // 64 floats
#define SM_BO    124160   // 6 floats (+pad)
#define SMEM_TOTAL 124192

__device__ __forceinline__ void mma16816(float& d0, float& d1, float& d2, float& d3,
                                         uint4 a, uint2 b) {
    asm volatile(
        "mma.sync.aligned.m16n8k16.row.col.f32.f16.f16.f32 "
        "{%0,%1,%2,%3}, {%4,%5,%6,%7}, {%8,%9}, {%0,%1,%2,%3};"
        : "+f"(d0), "+f"(d1), "+f"(d2), "+f"(d3)
        : "r"(a.x), "r"(a.y), "r"(a.z), "r"(a.w), "r"(b.x), "r"(b.y));
}

// pack two f32 -> f16x2 {lo=vlo, hi=vhi}
__device__ __forceinline__ uint32_t pk16(float vlo, float vhi) {
    uint32_t r;
    asm("cvt.rn.f16x2.f32 %0, %1, %2;" : "=r"(r) : "f"(vhi), "f"(vlo));
    return r;
}
__device__ __forceinline__ float2 h2f2(uint32_t h) {
    __half2 hh = *reinterpret_cast<__half2*>(&h);
    return __half22float2(hh);
}

__device__ __forceinline__ float wval(int m, int c,
                                      const float* __restrict__ w_def,
                                      const float* __restrict__ w_off) {
    if (m < 192) { int kk = m >> 6, o = m & 63; return __ldg(w_def + o * 192 + c * 3 + kk); }
    if (m < 210) { int t = m - 192; int kk = t / 6, j = t - 6 * kk;
                   return __ldg(w_off + j * 192 + c * 3 + kk); }
    return 0.f;
}

__global__ void __launch_bounds__(512, 1)
deform_hmma7_kernel(const float* __restrict__ x,
                    const float* __restrict__ w_off,
                    const float* __restrict__ b_off,
                    const float* __restrict__ w_def,
                    const float* __restrict__ b_def,
                    float* __restrict__ out)
{
    extern __shared__ char smem[];
    uint4*  WF  = (uint4*)(smem + SM_WF);
    float*  SCR = (float*)(smem + SM_SCR);
    float*  ZOF = (float*)(smem + SM_ZOFF);
    float*  BD  = (float*)(smem + SM_BD);
    float*  BO  = (float*)(smem + SM_BO);

    const int tid  = threadIdx.x;
    const int wid  = tid >> 5;        // warp = local site (0..15)
    const int lane = tid & 31;
    const int g    = lane >> 2;       // fragment row group
    const int q    = lane & 3;        // fragment col group

    const int bid = blockIdx.x;       // 0..1151
    const int b   = bid / 576;
    const int h   = (bid / 6) % 96;
    const int w0  = (bid % 6) * 16;
    const long xbase = (long)b * (64 * 16 * HW) + (long)h * 96 + w0;

    if (tid < 64) BD[tid] = b_def[tid];
    if (tid < 6)  BO[tid] = b_off[tid];

    // ---------------- stage X[c][s][n] -> SCR[c*276 + s*17 + n] ----------------
    {
        const float* xb = x + xbase;
        #pragma unroll 8
        for (int i = tid; i < 16384; i += 512) {
            int s = i & 15, n = (i >> 4) & 15, c = i >> 8;
            SCR[c * 276 + s * 17 + n] = xb[(long)(c * 16 + n) * HW + s];
        }
    }

    // ---------------- weight A-fragments (fp16 single) ----------------
    for (int idx = tid; idx < 14 * 4 * 32; idx += 512) {
        int l = idx & 31, rem = idx >> 5;
        int ks = rem & 3, oc = rem >> 2;
        int qq = l & 3, gg = l >> 2;
        int c0 = ks * 16 + qq * 2;
        int m0 = oc * 16 + gg, m1 = m0 + 8;
        uint32_t a0 = pk16(wval(m0, c0,     w_def, w_off), wval(m0, c0 + 1, w_def, w_off));
        uint32_t a1 = pk16(wval(m1, c0,     w_def, w_off), wval(m1, c0 + 1, w_def, w_off));
        uint32_t a2 = pk16(wval(m0, c0 + 8, w_def, w_off), wval(m0, c0 + 9, w_def, w_off));
        uint32_t a3 = pk16(wval(m1, c0 + 8, w_def, w_off), wval(m1, c0 + 9, w_def, w_off));
        WF[(oc * 4 + ks) * 32 + l] = make_uint4(a0, a1, a2, a3);
    }
    __syncthreads();

    // ---------------- X B-fragments -> registers (single fp16) ----------------
    uint2 bh[2][4];
    {
        const float* base = SCR + wid * 17;
        #pragma unroll
        for (int t = 0; t < 2; t++) {
            const int nn = t * 8 + g;
            #pragma unroll
            for (int ks = 0; ks < 4; ks++) {
                int c0 = ks * 16 + q * 2;
                float v0 = base[(c0    ) * 276 + nn];
                float v1 = base[(c0 + 1) * 276 + nn];
                float v2 = base[(c0 + 8) * 276 + nn];
                float v3 = base[(c0 + 9) * 276 + nn];
                bh[t][ks] = make_uint2(pk16(v0, v1), pk16(v2, v3));
            }
        }
    }

    // ---------------- offsets: stage-1 on oc 12,13, stash to ZOF ----------------
    float* zoff = ZOF + wid * 384;    // rows 0..17, stride 20
    #pragma unroll
    for (int oo = 0; oo < 2; oo++) {
        const int ocg = 12 + oo;
        uint4 au[4];
        #pragma unroll
        for (int ks = 0; ks < 4; ks++) au[ks] = WF[(ocg * 4 + ks) * 32 + lane];
        float d00 = 0.f, d01 = 0.f, d02 = 0.f, d03 = 0.f;
        float d10 = 0.f, d11 = 0.f, d12 = 0.f, d13 = 0.f;
        #pragma unroll
        for (int ks = 0; ks < 4; ks++) {
            mma16816(d00, d01, d02, d03, au[ks], bh[0][ks]);
            mma16816(d10, d11, d12, d13, au[ks], bh[1][ks]);
        }
        int r0 = oo * 16 + g;
        if (r0 < 18) {
            *(float2*)(zoff + r0 * 20 + q * 2)     = make_float2(d00, d01);
            *(float2*)(zoff + r0 * 20 + q * 2 + 8) = make_float2(d10, d11);
        }
        int r1 = r0 + 8;
        if (r1 < 18) {
            *(float2*)(zoff + r1 * 20 + q * 2)     = make_float2(d02, d03);
            *(float2*)(zoff + r1 * 20 + q * 2 + 8) = make_float2(d12, d13);
        }
    }
    __syncwarp();

    // ---------------- interpolation coefficients (lane owns n = lane&15) ----------------
    const int n = lane & 15;
    float W0c[3], W1c[3];
    int   s0c[3], s1c[3];
    {
        float offv[6];
        #pragma unroll
        for (int j = 0; j < 6; j++) {
            float v = BO[j];
            #pragma unroll
            for (int kk = 0; kk < 3; kk++) {
                int np = n - 1 + kk;
                if (np >= 0 && np < 16)
                    v += zoff[(kk * 6 + j) * 20 + np];
            }
            offv[j] = v;
        }
        #pragma unroll
        for (int k = 0; k < 3; k++) {
            float px  = (float)(n - 1 + k) + offv[2 * k + 1];
            float x0f = floorf(px);
            float fx  = px - x0f;
            int x0i = (int)x0f, x1i = x0i + 1;
            float wy = fmaxf(0.f, 1.f - fabsf(offv[2 * k]));
            W0c[k] = (x0i >= 0 && x0i < 16) ? (1.f - fx) * wy : 0.f;
            W1c[k] = (x1i >= 0 && x1i < 16) ? fx * wy : 0.f;
            s0c[k] = min(max(x0i, 0), 15);
            s1c[k] = min(max(x1i, 0), 15);
        }
    }

    // ---------------- output accumulators: out[o = oc*16+g(+8)][n = t*8+2q(+1)] ----------------
    float oa[4][2][4];
    #pragma unroll
    for (int oc = 0; oc < 4; oc++) {
        float bd0 = BD[oc * 16 + g];
        float bd1 = BD[oc * 16 + g + 8];
        #pragma unroll
        for (int t = 0; t < 2; t++) {
            oa[oc][t][0] = bd0; oa[oc][t][1] = bd0;
            oa[oc][t][2] = bd1; oa[oc][t][3] = bd1;
        }
    }

    // ---------------- main: per k, stage-1 GEMM + stage-2 gather-MMA ----------------
    #pragma unroll
    for (int k3 = 0; k3 < 3; k3++) {
        // build G B-frags: G[s][n] = W0(n)*(s==s0(n)) + W1(n)*(s==s1(n)), split hi/lo
        uint2 gh[2], gl[2];
        #pragma unroll
        for (int t = 0; t < 2; t++) {
            int nn = t * 8 + g;
            float w0v = __shfl_sync(0xffffffffu, W0c[k3], nn);
            float w1v = __shfl_sync(0xffffffffu, W1c[k3], nn);
            int   s0v = __shfl_sync(0xffffffffu, s0c[k3], nn);
            int   s1v = __shfl_sync(0xffffffffu, s1c[k3], nn);
            float gv[4];
            #pragma unroll
            for (int i = 0; i < 4; i++) {
                int s = q * 2 + (i & 1) + (i >> 1) * 8;
                gv[i] = ((s == s0v) ? w0v : 0.f) + ((s == s1v) ? w1v : 0.f);
            }
            uint32_t h01 = pk16(gv[0], gv[1]);
            uint32_t h23 = pk16(gv[2], gv[3]);
            float2 f01 = h2f2(h01);
            float2 f23 = h2f2(h23);
            gh[t] = make_uint2(h01, h23);
            gl[t] = make_uint2(pk16(gv[0] - f01.x, gv[1] - f01.y),
                               pk16(gv[2] - f23.x, gv[3] - f23.y));
        }

        #pragma unroll
        for (int oc = 0; oc < 4; oc++) {
            const int ocg = k3 * 4 + oc;
            uint4 au[4];
            #pragma unroll
            for (int ks = 0; ks < 4; ks++) au[ks] = WF[(ocg * 4 + ks) * 32 + lane];
            float d00 = 0.f, d01 = 0.f, d02 = 0.f, d03 = 0.f;
            float d10 = 0.f, d11 = 0.f, d12 = 0.f, d13 = 0.f;
            #pragma unroll
            for (int ks = 0; ks < 4; ks++) {
                mma16816(d00, d01, d02, d03, au[ks], bh[0][ks]);
                mma16816(d10, d11, d12, d13, au[ks], bh[1][ks]);
            }
            // Z^T D-frag -> stage-2 A-frag (fp16), layouts match directly
            uint4 za = make_uint4(pk16(d00, d01), pk16(d02, d03),
                                  pk16(d10, d11), pk16(d12, d13));
            mma16816(oa[oc][0][0], oa[oc][0][1], oa[oc][0][2], oa[oc][0][3], za, gh[0]);
            mma16816(oa[oc][0][0], oa[oc][0][1], oa[oc][0][2], oa[oc][0][3], za, gl[0]);
            mma16816(oa[oc][1][0], oa[oc][1][1], oa[oc][1][2], oa[oc][1][3], za, gh[1]);
            mma16816(oa[oc][1][0], oa[oc][1][1], oa[oc][1][2], oa[oc][1][3], za, gl[1]);
        }
    }

    // ---------------- staged coalesced store ----------------
    __syncthreads();   // everyone done with SCR (X staging) and ZOF
    {
        float* STG2 = SCR;
        #pragma unroll
        for (int oc = 0; oc < 4; oc++) {
            #pragma unroll
            for (int t = 0; t < 2; t++) {
                #pragma unroll
                for (int r = 0; r < 4; r++) {
                    int o  = oc * 16 + g + ((r >> 1) << 3);
                    int nn = t * 8 + 2 * q + (r & 1);
                    int ph = (o & 7) | (((nn >> 1) & 1) << 3);
                    STG2[(o * 16 + nn) * 16 + (wid ^ ph)] = oa[oc][t][r];
                }
            }
        }
    }
    __syncthreads();
    {
        const float* STG2 = SCR;
        float* ob = out + xbase;
        #pragma unroll 8
        for (int idx = tid; idx < 16384; idx += 512) {
            int s = idx & 15, on = idx >> 4;
            int o = on >> 4, nn = on & 15;
            int ph = (o & 7) | (((nn >> 1) & 1) << 3);
            ob[(long)on * HW + s] = STG2[on * 16 + (s ^ ph)];
        }
    }
}

extern "C" void kernel_launch(void* const* d_in, const int* in_sizes, int n_in,
                              void* d_out, int out_size)
{
    const float* x     = (const float*)d_in[0];
    const float* w_off = (const float*)d_in[1];
    const float* b_off = (const float*)d_in[2];
    const float* w_def = (const float*)d_in[3];
    const float* b_def = (const float*)d_in[4];
    float* out = (float*)d_out;

    cudaFuncSetAttribute(deform_hmma7_kernel,
                         cudaFuncAttributeMaxDynamicSharedMemorySize, SMEM_TOTAL);

    // 2 (B) * 96 (H) * 6 (W/16) = 1152 CTAs, 512 threads
    deform_hmma7_kernel<<<1152, 512, SMEM_TOTAL>>>(x, w_off, b_off, w_def, b_def, out);
}

// round 11
// speedup vs baseline: 1.5426x; 1.1455x over previous
#include <cuda_runtime.h>
#include <cuda_fp16.h>
#include <cstdint>

// DeformableFusionAcrossFocus R10: two-stage HMMA, gather-as-MMA, single-pass X,
// + weight fragments precomputed ONCE by a prep kernel into __device__ global buffer
//   (was: every CTA re-did 28K scattered scalar loads + packs).
// Stage 1 (per site-warp): Z^T[m,n'] = sum_c W[m,c] * X[c,n']   (A=weights fp16, B=X fp16)
// Stage 2: out[o,n] += Z^T[o,s] * G[s,n],  G = interp matrix, fp16 Gh+Gl split.

#define HW 9216
#define NWF 1792     // 14 oc-groups * 4 ks * 32 lanes

// ---- smem byte layout ----
#define SM_WF    0        // weight A-frags [oc14][ks4][lane32] uint4 = 28672
#define SM_SCR   28672    // X staging 17664 floats = 70656B; reused as STG2 (16384 floats)
#define SM_ZOFF  99328    // per-warp offset buffer: 16 * 384 floats = 24576B
#define SM_BD    123904   // 64 floats
#define SM_BO    124160   // 6 floats (+pad)
#define SMEM_TOTAL 124192

__device__ uint4 g_WF[NWF];

__device__ __forceinline__ void mma16816(float& d0, float& d1, float& d2, float& d3,
                                         uint4 a, uint2 b) {
    asm volatile(
        "mma.sync.aligned.m16n8k16.row.col.f32.f16.f16.f32 "
        "{%0,%1,%2,%3}, {%4,%5,%6,%7}, {%8,%9}, {%0,%1,%2,%3};"
        : "+f"(d0), "+f"(d1), "+f"(d2), "+f"(d3)
        : "r"(a.x), "r"(a.y), "r"(a.z), "r"(a.w), "r"(b.x), "r"(b.y));
}

// pack two f32 -> f16x2 {lo=vlo, hi=vhi}
__device__ __forceinline__ uint32_t pk16(float vlo, float vhi) {
    uint32_t r;
    asm("cvt.rn.f16x2.f32 %0, %1, %2;" : "=r"(r) : "f"(vhi), "f"(vlo));
    return r;
}
__device__ __forceinline__ float2 h2f2(uint32_t h) {
    __half2 hh = *reinterpret_cast<__half2*>(&h);
    return __half22float2(hh);
}

__device__ __forceinline__ float wval(int m, int c,
                                      const float* __restrict__ w_def,
                                      const float* __restrict__ w_off) {
    if (m < 192) { int kk = m >> 6, o = m & 63; return __ldg(w_def + o * 192 + c * 3 + kk); }
    if (m < 210) { int t = m - 192; int kk = t / 6, j = t - 6 * kk;
                   return __ldg(w_off + j * 192 + c * 3 + kk); }
    return 0.f;
}

// ---------------- prep: build weight A-fragments once ----------------
__global__ void deform_prep_kernel(const float* __restrict__ w_off,
                                   const float* __restrict__ w_def)
{
    int idx = blockIdx.x * blockDim.x + threadIdx.x;
    if (idx >= NWF) return;
    int l = idx & 31, rem = idx >> 5;
    int ks = rem & 3, oc = rem >> 2;
    int qq = l & 3, gg = l >> 2;
    int c0 = ks * 16 + qq * 2;
    int m0 = oc * 16 + gg, m1 = m0 + 8;
    uint32_t a0 = pk16(wval(m0, c0,     w_def, w_off), wval(m0, c0 + 1, w_def, w_off));
    uint32_t a1 = pk16(wval(m1, c0,     w_def, w_off), wval(m1, c0 + 1, w_def, w_off));
    uint32_t a2 = pk16(wval(m0, c0 + 8, w_def, w_off), wval(m0, c0 + 9, w_def, w_off));
    uint32_t a3 = pk16(wval(m1, c0 + 8, w_def, w_off), wval(m1, c0 + 9, w_def, w_off));
    g_WF[(oc * 4 + ks) * 32 + l] = make_uint4(a0, a1, a2, a3);
}

__global__ void __launch_bounds__(512, 1)
deform_hmma8_kernel(const float* __restrict__ x,
                    const float* __restrict__ b_off,
                    const float* __restrict__ b_def,
                    float* __restrict__ out)
{
    extern __shared__ char smem[];
    uint4*  WF  = (uint4*)(smem + SM_WF);
    float*  SCR = (float*)(smem + SM_SCR);
    float*  ZOF = (float*)(smem + SM_ZOFF);
    float*  BD  = (float*)(smem + SM_BD);
    float*  BO  = (float*)(smem + SM_BO);

    const int tid  = threadIdx.x;
    const int wid  = tid >> 5;        // warp = local site (0..15)
    const int lane = tid & 31;
    const int g    = lane >> 2;       // fragment row group
    const int q    = lane & 3;        // fragment col group

    const int bid = blockIdx.x;       // 0..1151
    const int b   = bid / 576;
    const int h   = (bid / 6) % 96;
    const int w0  = (bid % 6) * 16;
    const long xbase = (long)b * (64 * 16 * HW) + (long)h * 96 + w0;

    if (tid < 64) BD[tid] = b_def[tid];
    if (tid < 6)  BO[tid] = b_off[tid];

    // ---------------- stage X[c][s][n] -> SCR[c*276 + s*17 + n] ----------------
    {
        const float* xb = x + xbase;
        #pragma unroll 8
        for (int i = tid; i < 16384; i += 512) {
            int s = i & 15, n = (i >> 4) & 15, c = i >> 8;
            SCR[c * 276 + s * 17 + n] = xb[(long)(c * 16 + n) * HW + s];
        }
    }

    // ---------------- weight A-fragments: coalesced copy from prebuilt buffer ----------------
    #pragma unroll 4
    for (int i = tid; i < NWF; i += 512)
        WF[i] = g_WF[i];
    __syncthreads();

    // ---------------- X B-fragments -> registers (single fp16) ----------------
    uint2 bh[2][4];
    {
        const float* base = SCR + wid * 17;
        #pragma unroll
        for (int t = 0; t < 2; t++) {
            const int nn = t * 8 + g;
            #pragma unroll
            for (int ks = 0; ks < 4; ks++) {
                int c0 = ks * 16 + q * 2;
                float v0 = base[(c0    ) * 276 + nn];
                float v1 = base[(c0 + 1) * 276 + nn];
                float v2 = base[(c0 + 8) * 276 + nn];
                float v3 = base[(c0 + 9) * 276 + nn];
                bh[t][ks] = make_uint2(pk16(v0, v1), pk16(v2, v3));
            }
        }
    }

    // ---------------- offsets: stage-1 on oc 12,13, stash to ZOF ----------------
    float* zoff = ZOF + wid * 384;    // rows 0..17, stride 20
    #pragma unroll
    for (int oo = 0; oo < 2; oo++) {
        const int ocg = 12 + oo;
        uint4 au[4];
        #pragma unroll
        for (int ks = 0; ks < 4; ks++) au[ks] = WF[(ocg * 4 + ks) * 32 + lane];
        float d00 = 0.f, d01 = 0.f, d02 = 0.f, d03 = 0.f;
        float d10 = 0.f, d11 = 0.f, d12 = 0.f, d13 = 0.f;
        #pragma unroll
        for (int ks = 0; ks < 4; ks++) {
            mma16816(d00, d01, d02, d03, au[ks], bh[0][ks]);
            mma16816(d10, d11, d12, d13, au[ks], bh[1][ks]);
        }
        int r0 = oo * 16 + g;
        if (r0 < 18) {
            *(float2*)(zoff + r0 * 20 + q * 2)     = make_float2(d00, d01);
            *(float2*)(zoff + r0 * 20 + q * 2 + 8) = make_float2(d10, d11);
        }
        int r1 = r0 + 8;
        if (r1 < 18) {
            *(float2*)(zoff + r1 * 20 + q * 2)     = make_float2(d02, d03);
            *(float2*)(zoff + r1 * 20 + q * 2 + 8) = make_float2(d12, d13);
        }
    }
    __syncwarp();

    // ---------------- interpolation coefficients (lane owns n = lane&15) ----------------
    const int n = lane & 15;
    float W0c[3], W1c[3];
    int   s0c[3], s1c[3];
    {
        float offv[6];
        #pragma unroll
        for (int j = 0; j < 6; j++) {
            float v = BO[j];
            #pragma unroll
            for (int kk = 0; kk < 3; kk++) {
                int np = n - 1 + kk;
                if (np >= 0 && np < 16)
                    v += zoff[(kk * 6 + j) * 20 + np];
            }
            offv[j] = v;
        }
        #pragma unroll
        for (int k = 0; k < 3; k++) {
            float px  = (float)(n - 1 + k) + offv[2 * k + 1];
            float x0f = floorf(px);
            float fx  = px - x0f;
            int x0i = (int)x0f, x1i = x0i + 1;
            float wy = fmaxf(0.f, 1.f - fabsf(offv[2 * k]));
            W0c[k] = (x0i >= 0 && x0i < 16) ? (1.f - fx) * wy : 0.f;
            W1c[k] = (x1i >= 0 && x1i < 16) ? fx * wy : 0.f;
            s0c[k] = min(max(x0i, 0), 15);
            s1c[k] = min(max(x1i, 0), 15);
        }
    }

    // ---------------- output accumulators: out[o = oc*16+g(+8)][n = t*8+2q(+1)] ----------------
    float oa[4][2][4];
    #pragma unroll
    for (int oc = 0; oc < 4; oc++) {
        float bd0 = BD[oc * 16 + g];
        float bd1 = BD[oc * 16 + g + 8];
        #pragma unroll
        for (int t = 0; t < 2; t++) {
            oa[oc][t][0] = bd0; oa[oc][t][1] = bd0;
            oa[oc][t][2] = bd1; oa[oc][t][3] = bd1;
        }
    }

    // ---------------- main: per k, stage-1 GEMM + stage-2 gather-MMA ----------------
    #pragma unroll
    for (int k3 = 0; k3 < 3; k3++) {
        // build G B-frags: G[s][n] = W0(n)*(s==s0(n)) + W1(n)*(s==s1(n)), split hi/lo
        uint2 gh[2], gl[2];
        #pragma unroll
        for (int t = 0; t < 2; t++) {
            int nn = t * 8 + g;
            float w0v = __shfl_sync(0xffffffffu, W0c[k3], nn);
            float w1v = __shfl_sync(0xffffffffu, W1c[k3], nn);
            int   s0v = __shfl_sync(0xffffffffu, s0c[k3], nn);
            int   s1v = __shfl_sync(0xffffffffu, s1c[k3], nn);
            float gv[4];
            #pragma unroll
            for (int i = 0; i < 4; i++) {
                int s = q * 2 + (i & 1) + (i >> 1) * 8;
                gv[i] = ((s == s0v) ? w0v : 0.f) + ((s == s1v) ? w1v : 0.f);
            }
            uint32_t h01 = pk16(gv[0], gv[1]);
            uint32_t h23 = pk16(gv[2], gv[3]);
            float2 f01 = h2f2(h01);
            float2 f23 = h2f2(h23);
            gh[t] = make_uint2(h01, h23);
            gl[t] = make_uint2(pk16(gv[0] - f01.x, gv[1] - f01.y),
                               pk16(gv[2] - f23.x, gv[3] - f23.y));
        }

        #pragma unroll
        for (int oc = 0; oc < 4; oc++) {
            const int ocg = k3 * 4 + oc;
            uint4 au[4];
            #pragma unroll
            for (int ks = 0; ks < 4; ks++) au[ks] = WF[(ocg * 4 + ks) * 32 + lane];
            float d00 = 0.f, d01 = 0.f, d02 = 0.f, d03 = 0.f;
            float d10 = 0.f, d11 = 0.f, d12 = 0.f, d13 = 0.f;
            #pragma unroll
            for (int ks = 0; ks < 4; ks++) {
                mma16816(d00, d01, d02, d03, au[ks], bh[0][ks]);
                mma16816(d10, d11, d12, d13, au[ks], bh[1][ks]);
            }
            // Z^T D-frag -> stage-2 A-frag (fp16), layouts match directly
            uint4 za = make_uint4(pk16(d00, d01), pk16(d02, d03),
                                  pk16(d10, d11), pk16(d12, d13));
            mma16816(oa[oc][0][0], oa[oc][0][1], oa[oc][0][2], oa[oc][0][3], za, gh[0]);
            mma16816(oa[oc][0][0], oa[oc][0][1], oa[oc][0][2], oa[oc][0][3], za, gl[0]);
            mma16816(oa[oc][1][0], oa[oc][1][1], oa[oc][1][2], oa[oc][1][3], za, gh[1]);
            mma16816(oa[oc][1][0], oa[oc][1][1], oa[oc][1][2], oa[oc][1][3], za, gl[1]);
        }
    }

    // ---------------- staged coalesced store ----------------
    __syncthreads();   // everyone done with SCR (X staging) and ZOF
    {
        float* STG2 = SCR;
        #pragma unroll
        for (int oc = 0; oc < 4; oc++) {
            #pragma unroll
            for (int t = 0; t < 2; t++) {
                #pragma unroll
                for (int r = 0; r < 4; r++) {
                    int o  = oc * 16 + g + ((r >> 1) << 3);
                    int nn = t * 8 + 2 * q + (r & 1);
                    int ph = (o & 7) | (((nn >> 1) & 1) << 3);
                    STG2[(o * 16 + nn) * 16 + (wid ^ ph)] = oa[oc][t][r];
                }
            }
        }
    }
    __syncthreads();
    {
        const float* STG2 = SCR;
        float* ob = out + xbase;
        #pragma unroll 8
        for (int idx = tid; idx < 16384; idx += 512) {
            int s = idx & 15, on = idx >> 4;
            int o = on >> 4, nn = on & 15;
            int ph = (o & 7) | (((nn >> 1) & 1) << 3);
            ob[(long)on * HW + s] = STG2[on * 16 + (s ^ ph)];
        }
    }
}

extern "C" void kernel_launch(void* const* d_in, const int* in_sizes, int n_in,
                              void* d_out, int out_size)
{
    const float* x     = (const float*)d_in[0];
    const float* w_off = (const float*)d_in[1];
    const float* b_off = (const float*)d_in[2];
    const float* w_def = (const float*)d_in[3];
    const float* b_def = (const float*)d_in[4];
    float* out = (float*)d_out;

    cudaFuncSetAttribute(deform_hmma8_kernel,
                         cudaFuncAttributeMaxDynamicSharedMemorySize, SMEM_TOTAL);

    // prep: build weight fragments once (7 CTAs x 256 covers 1792 entries)
    deform_prep_kernel<<<7, 256>>>(w_off, w_def);
    // main: 2 (B) * 96 (H) * 6 (W/16) = 1152 CTAs, 512 threads
    deform_hmma8_kernel<<<1152, 512, SMEM_TOTAL>>>(x, b_off, b_def, out);
}